// round 2
// baseline (speedup 1.0000x reference)
#include <cuda_runtime.h>
#include <math.h>

// Problem constants
#define BB 4
#define NN 4096
#define CC 1024
#define HH 16
#define DD 64
#define MM (BB*NN)   // 16384

// ---------------- scratch (device globals; no allocation) ----------------
__device__ float g_W[(size_t)MM * CC];     // qkv projection result [b,n,c]
__device__ float g_T[(size_t)MM * CC];     // gated output pre-GEMM2 [b,n,c]
__device__ float g_pi[(size_t)MM * HH];    // softmax pi [b,n,h]
__device__ float g_norm2[BB * CC];         // sum_n w^2 per (b,c)
__device__ float g_dots[BB * CC];          // sum_n pi * w^2 per (b,c)
__device__ float g_attn[BB * CC];          // 1/(1+dots/sumpi)
__device__ float g_sumpi[BB * HH];         // sum_n pi per (b,h)

// ---------------- SGEMM (NT): C[m,n] = sum_k A[m,k]*B[n,k] (+bias[n]) -----
// 128x128 tile, BK=8, 256 threads, 8x8 per thread.
__global__ __launch_bounds__(256) void sgemm_nt_kernel(
    const float* __restrict__ A, const float* __restrict__ B,
    const float* __restrict__ bias, float* __restrict__ C,
    int M, int N, int K)
{
    __shared__ float As[8][128];
    __shared__ float Bs[8][128];
    const int tid  = threadIdx.x;
    const int m0   = blockIdx.y * 128;
    const int n0   = blockIdx.x * 128;
    const int lrow = tid >> 1;          // 0..127
    const int lcol = (tid & 1) << 2;    // 0 or 4
    const int tx   = tid & 15;
    const int ty   = tid >> 4;

    const float* Ap = A + (size_t)(m0 + lrow) * K + lcol;
    const float* Bp = B + (size_t)(n0 + lrow) * K + lcol;

    float acc[8][8];
    #pragma unroll
    for (int i = 0; i < 8; i++)
        #pragma unroll
        for (int j = 0; j < 8; j++) acc[i][j] = 0.f;

    for (int k0 = 0; k0 < K; k0 += 8) {
        float4 av = *reinterpret_cast<const float4*>(Ap + k0);
        float4 bv = *reinterpret_cast<const float4*>(Bp + k0);
        __syncthreads();
        As[lcol+0][lrow] = av.x; As[lcol+1][lrow] = av.y;
        As[lcol+2][lrow] = av.z; As[lcol+3][lrow] = av.w;
        Bs[lcol+0][lrow] = bv.x; Bs[lcol+1][lrow] = bv.y;
        Bs[lcol+2][lrow] = bv.z; Bs[lcol+3][lrow] = bv.w;
        __syncthreads();
        #pragma unroll
        for (int k = 0; k < 8; k++) {
            float a[8], b[8];
            *reinterpret_cast<float4*>(a)   = *reinterpret_cast<const float4*>(&As[k][ty*8]);
            *reinterpret_cast<float4*>(a+4) = *reinterpret_cast<const float4*>(&As[k][ty*8+4]);
            *reinterpret_cast<float4*>(b)   = *reinterpret_cast<const float4*>(&Bs[k][tx*8]);
            *reinterpret_cast<float4*>(b+4) = *reinterpret_cast<const float4*>(&Bs[k][tx*8+4]);
            #pragma unroll
            for (int i = 0; i < 8; i++)
                #pragma unroll
                for (int j = 0; j < 8; j++)
                    acc[i][j] = fmaf(a[i], b[j], acc[i][j]);
        }
    }

    #pragma unroll
    for (int i = 0; i < 8; i++) {
        const int m = m0 + ty*8 + i;
        float* Cp = C + (size_t)m * N + n0 + tx*8;
        #pragma unroll
        for (int j = 0; j < 8; j += 4) {
            float4 v;
            v.x = acc[i][j+0]; v.y = acc[i][j+1];
            v.z = acc[i][j+2]; v.w = acc[i][j+3];
            if (bias) {
                const float* bp = bias + n0 + tx*8 + j;
                v.x += bp[0]; v.y += bp[1]; v.z += bp[2]; v.w += bp[3];
            }
            *reinterpret_cast<float4*>(Cp + j) = v;
        }
    }
}

// ---------------- norm2 over token axis: norm2[b,c] = sum_n W[b,n,c]^2 ----
// grid (CC/256, BB, 8 n-splits), block 256
__global__ __launch_bounds__(256) void norm2_kernel(
    const float* __restrict__ W, float* __restrict__ norm2)
{
    const int c  = blockIdx.x * 256 + threadIdx.x;
    const int b  = blockIdx.y;
    const int nc = blockIdx.z;
    const float* p = W + ((size_t)b * NN + (size_t)nc * (NN/8)) * CC + c;
    float s = 0.f;
    #pragma unroll 8
    for (int n = 0; n < NN/8; n++) {
        float v = p[(size_t)n * CC];
        s = fmaf(v, v, s);
    }
    atomicAdd(&norm2[b * CC + c], s);
}

// ---------------- pi + reductions -----------------------------------------
// One block = 16 rows (same b). 256 threads, thread t owns c = 4t..4t+3,
// head h = t/16. Computes s, softmax over 16 heads, writes pi, accumulates
// sum_n pi (per head) and sum_n pi*w^2 (per c), flushed with atomics.
__global__ __launch_bounds__(256) void pi_kernel(
    const float* __restrict__ W, const float* __restrict__ norm2,
    const float* __restrict__ temp,
    float* __restrict__ pi_out, float* __restrict__ dots,
    float* __restrict__ sumpi)
{
    const int tid  = threadIdx.x;
    const int m0   = blockIdx.x * 16;
    const int b    = m0 >> 12;          // / NN
    const int c0   = tid * 4;
    const int h    = tid >> 4;
    const int lane = tid & 31;

    __shared__ float s_head[16];
    __shared__ float s_pi[16];

    float inv2[4];
    #pragma unroll
    for (int i = 0; i < 4; i++) {
        float nrm = sqrtf(norm2[b * CC + c0 + i]);
        float inv = 1.0f / fmaxf(nrm, 1e-12f);
        inv2[i] = inv * inv;
    }
    const float tmult = temp[h];

    float accD[4] = {0.f, 0.f, 0.f, 0.f};
    float sumPiLoc = 0.f;

    for (int r = 0; r < 16; r++) {
        const int m = m0 + r;
        float4 w4 = *reinterpret_cast<const float4*>(&W[(size_t)m * CC + c0]);
        float sq[4] = {w4.x*w4.x, w4.y*w4.y, w4.z*w4.z, w4.w*w4.w};
        float part = sq[0]*inv2[0] + sq[1]*inv2[1] + sq[2]*inv2[2] + sq[3]*inv2[3];
        part += __shfl_xor_sync(0xffffffffu, part, 8);
        part += __shfl_xor_sync(0xffffffffu, part, 4);
        part += __shfl_xor_sync(0xffffffffu, part, 2);
        part += __shfl_xor_sync(0xffffffffu, part, 1);
        if ((lane & 15) == 0) s_head[h] = part * tmult;
        __syncthreads();
        if (tid < 16) {
            float v  = s_head[tid];
            float mx = v;
            #pragma unroll
            for (int o = 8; o; o >>= 1) mx = fmaxf(mx, __shfl_xor_sync(0x0000ffffu, mx, o));
            float e  = expf(v - mx);
            float se = e;
            #pragma unroll
            for (int o = 8; o; o >>= 1) se += __shfl_xor_sync(0x0000ffffu, se, o);
            float p = e / se;
            s_pi[tid]  = p;
            sumPiLoc  += p;
            pi_out[(size_t)m * HH + tid] = p;
        }
        __syncthreads();
        const float ph = s_pi[h];
        #pragma unroll
        for (int i = 0; i < 4; i++) accD[i] = fmaf(ph, sq[i], accD[i]);
    }

    #pragma unroll
    for (int i = 0; i < 4; i++)
        atomicAdd(&dots[b * CC + c0 + i], accD[i]);
    if (tid < 16)
        atomicAdd(&sumpi[b * HH + tid], sumPiLoc);
}

// ---------------- attn finalize: attn = 1/(1 + dots/(sumpi+1e-8)) ---------
__global__ void attn_kernel(const float* __restrict__ dots,
                            const float* __restrict__ sumpi,
                            float* __restrict__ attn)
{
    const int i = blockIdx.x * 256 + threadIdx.x;   // 0..4095
    const int b = i >> 10;
    const int h = (i >> 6) & 15;
    const float dn = dots[i] / (sumpi[b * HH + h] + 1e-8f);
    attn[i] = 1.0f / (1.0f + dn);
}

// ---------------- elementwise gate: T = -W * pi[b,n,h] * attn[b,c] --------
__global__ __launch_bounds__(256) void gate_kernel(
    const float* __restrict__ W, const float* __restrict__ pi,
    const float* __restrict__ attn, float* __restrict__ T)
{
    const size_t idx  = (size_t)blockIdx.x * 256 + threadIdx.x;  // float4 index
    const size_t base = idx * 4;
    const int m = (int)(base >> 10);
    const int c = (int)(base & (CC - 1));
    const int b = m >> 12;
    const int h = c >> 6;
    float4 w4 = *reinterpret_cast<const float4*>(W + base);
    float4 a4 = *reinterpret_cast<const float4*>(attn + b * CC + c);
    const float p = -pi[(size_t)m * HH + h];
    float4 o;
    o.x = w4.x * p * a4.x;
    o.y = w4.y * p * a4.y;
    o.z = w4.z * p * a4.z;
    o.w = w4.w * p * a4.w;
    *reinterpret_cast<float4*>(T + base) = o;
}

// ---------------- launch ---------------------------------------------------
extern "C" void kernel_launch(void* const* d_in, const int* in_sizes, int n_in,
                              void* d_out, int out_size)
{
    const float* x     = (const float*)d_in[0];
    const float* qkv_w = (const float*)d_in[1];
    const float* temp  = (const float*)d_in[2];
    const float* out_w = (const float*)d_in[3];
    const float* out_b = (const float*)d_in[4];
    float* y = (float*)d_out;

    float *W, *T, *pi, *nrm, *dots, *attn, *sp;
    cudaGetSymbolAddress((void**)&W,    g_W);
    cudaGetSymbolAddress((void**)&T,    g_T);
    cudaGetSymbolAddress((void**)&pi,   g_pi);
    cudaGetSymbolAddress((void**)&nrm,  g_norm2);
    cudaGetSymbolAddress((void**)&dots, g_dots);
    cudaGetSymbolAddress((void**)&attn, g_attn);
    cudaGetSymbolAddress((void**)&sp,   g_sumpi);

    cudaMemsetAsync(nrm,  0, BB * CC * sizeof(float));
    cudaMemsetAsync(dots, 0, BB * CC * sizeof(float));
    cudaMemsetAsync(sp,   0, BB * HH * sizeof(float));

    dim3 gemm_grid(CC / 128, MM / 128);   // (8, 128)

    // 1) W = x @ qkv_w^T
    sgemm_nt_kernel<<<gemm_grid, 256>>>(x, qkv_w, nullptr, W, MM, CC, CC);
    // 2) norm2 over tokens
    norm2_kernel<<<dim3(CC / 256, BB, 8), 256>>>(W, nrm);
    // 3) pi + sum_n pi + sum_n pi*w^2
    pi_kernel<<<MM / 16, 256>>>(W, nrm, temp, pi, dots, sp);
    // 4) attn
    attn_kernel<<<(BB * CC) / 256, 256>>>(dots, sp, attn);
    // 5) gate
    gate_kernel<<<(int)(((size_t)MM * CC / 4) / 256), 256>>>(W, pi, attn, T);
    // 6) y = T @ out_w^T + out_b
    sgemm_nt_kernel<<<gemm_grid, 256>>>(T, out_w, out_b, y, MM, CC, CC);
}

// round 5
// speedup vs baseline: 2.7836x; 2.7836x over previous
#include <cuda_runtime.h>
#include <cuda_bf16.h>
#include <cstdint>
#include <math.h>

// Problem constants
#define BB 4
#define NN 4096
#define CC 1024
#define HH 16
#define MM (BB*NN)   // 16384

// ---------------- scratch (device globals; no allocation) ----------------
__device__ float g_W[(size_t)MM * CC];            // qkv projection result fp32
__device__ __nv_bfloat16 g_Ahi[(size_t)MM * CC];  // split of x, later of T
__device__ __nv_bfloat16 g_Alo[(size_t)MM * CC];
__device__ __nv_bfloat16 g_B1hi[(size_t)CC * CC]; // qkv_w split
__device__ __nv_bfloat16 g_B1lo[(size_t)CC * CC];
__device__ __nv_bfloat16 g_B2hi[(size_t)CC * CC]; // out_w split
__device__ __nv_bfloat16 g_B2lo[(size_t)CC * CC];
__device__ float g_pi[(size_t)MM * HH];
__device__ float g_norm2[BB * CC];
__device__ float g_dots[BB * CC];
__device__ float g_attn[BB * CC];
__device__ float g_sumpi[BB * HH];

// ---------------- PTX helpers ---------------------------------------------
__device__ __forceinline__ uint32_t smem_u32(const void* p) {
    uint32_t a;
    asm("{ .reg .u64 t; cvta.to.shared.u64 t, %1; cvt.u32.u64 %0, t; }" : "=r"(a) : "l"(p));
    return a;
}
#define CP_ASYNC16(dst, src) \
    asm volatile("cp.async.cg.shared.global [%0], [%1], 16;" :: "r"(dst), "l"(src) : "memory")
#define CP_COMMIT() asm volatile("cp.async.commit_group;" ::: "memory")
#define CP_WAIT2()  asm volatile("cp.async.wait_group 2;" ::: "memory")

__device__ __forceinline__ void ldsm4(uint32_t* r, uint32_t addr) {
    asm volatile("ldmatrix.sync.aligned.m8n8.x4.shared.b16 {%0,%1,%2,%3}, [%4];"
        : "=r"(r[0]), "=r"(r[1]), "=r"(r[2]), "=r"(r[3]) : "r"(addr));
}
__device__ __forceinline__ void mma16816(float* c, const uint32_t* a, const uint32_t* b) {
    asm volatile("mma.sync.aligned.m16n8k16.row.col.f32.bf16.bf16.f32 "
        "{%0,%1,%2,%3}, {%4,%5,%6,%7}, {%8,%9}, {%0,%1,%2,%3};"
        : "+f"(c[0]), "+f"(c[1]), "+f"(c[2]), "+f"(c[3])
        : "r"(a[0]), "r"(a[1]), "r"(a[2]), "r"(a[3]), "r"(b[0]), "r"(b[1]));
}

// smem tile: 128 rows x 32 bf16 (64B/row). Swizzle 16B chunks by ((row>>1)&3)<<4.
__device__ __forceinline__ uint32_t tswz(int row, int kb) {
    return (uint32_t)(row * 64 + (kb ^ (((row >> 1) & 3) << 4)));
}

// ---------------- bf16x3 HMMA GEMM: C[m,n] = sum_k A[m,k]*B[n,k] (+bias) --
// Tile 128x128, BK=32, 256 threads (warps 2m x 4n, 64x32 each), 3-stage pipe.
#define STG_BYTES 32768     // 4 sub-tiles x 8KB per stage
#define OFF_AHI 0
#define OFF_ALO 8192
#define OFF_BHI 16384
#define OFF_BLO 24576

__global__ __launch_bounds__(256) void gemm_bf16x3(
    const __nv_bfloat16* __restrict__ Ahi, const __nv_bfloat16* __restrict__ Alo,
    const __nv_bfloat16* __restrict__ Bhi, const __nv_bfloat16* __restrict__ Blo,
    const float* __restrict__ bias, float* __restrict__ C, int M, int N, int K)
{
    extern __shared__ __align__(1024) char smem[];
    const uint32_t sm_base = smem_u32(smem);

    const int tid  = threadIdx.x;
    const int lane = tid & 31;
    const int wid  = tid >> 5;
    const int mw   = wid >> 2;        // 0..1
    const int nw   = wid & 3;         // 0..3
    const int m0   = blockIdx.y * 128;
    const int n0   = blockIdx.x * 128;

    // ---- loader mapping: thread -> (row, 16B chunk) -----------------------
    const int lrow = tid >> 2;        // 0..63
    const int lk16 = tid & 3;         // 0..3
    const uint32_t dst_off0 = tswz(lrow,      lk16 * 16);
    const uint32_t dst_off1 = tswz(lrow + 64, lk16 * 16);
    const char* srcAh0 = (const char*)(Ahi + (size_t)(m0 + lrow)      * K) + lk16 * 16;
    const char* srcAh1 = (const char*)(Ahi + (size_t)(m0 + lrow + 64) * K) + lk16 * 16;
    const char* srcAl0 = (const char*)(Alo + (size_t)(m0 + lrow)      * K) + lk16 * 16;
    const char* srcAl1 = (const char*)(Alo + (size_t)(m0 + lrow + 64) * K) + lk16 * 16;
    const char* srcBh0 = (const char*)(Bhi + (size_t)(n0 + lrow)      * K) + lk16 * 16;
    const char* srcBh1 = (const char*)(Bhi + (size_t)(n0 + lrow + 64) * K) + lk16 * 16;
    const char* srcBl0 = (const char*)(Blo + (size_t)(n0 + lrow)      * K) + lk16 * 16;
    const char* srcBl1 = (const char*)(Blo + (size_t)(n0 + lrow + 64) * K) + lk16 * 16;

    const int NCHUNK = K / 32;        // 32

    auto load_stage = [&](int s) {
        const uint32_t sb = sm_base + (uint32_t)(s % 3) * STG_BYTES;
        const int kb = s * 64;        // byte offset along K
        CP_ASYNC16(sb + OFF_AHI + dst_off0, srcAh0 + kb);
        CP_ASYNC16(sb + OFF_AHI + dst_off1, srcAh1 + kb);
        CP_ASYNC16(sb + OFF_ALO + dst_off0, srcAl0 + kb);
        CP_ASYNC16(sb + OFF_ALO + dst_off1, srcAl1 + kb);
        CP_ASYNC16(sb + OFF_BHI + dst_off0, srcBh0 + kb);
        CP_ASYNC16(sb + OFF_BHI + dst_off1, srcBh1 + kb);
        CP_ASYNC16(sb + OFF_BLO + dst_off0, srcBl0 + kb);
        CP_ASYNC16(sb + OFF_BLO + dst_off1, srcBl1 + kb);
        CP_COMMIT();
    };

    // ---- per-warp ldmatrix address components -----------------------------
    // A tiles (m16 x k16): rows mw*64 + mi*16 + (lane&15); kb = ks*32 + ((lane>>4)<<4)
    uint32_t a_row_off[4];
    #pragma unroll
    for (int mi = 0; mi < 4; mi++) {
        int row = mw * 64 + mi * 16 + (lane & 15);
        a_row_off[mi] = (uint32_t)(row * 64) ;
        a_row_off[mi] |= ((uint32_t)(((row >> 1) & 3) << 4)) << 16; // pack swz in hi bits
    }
    const uint32_t a_kb_lane = (uint32_t)((lane >> 4) << 4);
    // B tiles (n16 x k16): rows nw*32 + g*16 + (lane&7) + ((lane>>4)<<3); kb = ks*32 + ((lane&8)<<1)
    uint32_t b_row_off[2];
    #pragma unroll
    for (int g = 0; g < 2; g++) {
        int row = nw * 32 + g * 16 + (lane & 7) + ((lane >> 4) << 3);
        b_row_off[g] = (uint32_t)(row * 64);
        b_row_off[g] |= ((uint32_t)(((row >> 1) & 3) << 4)) << 16;
    }
    const uint32_t b_kb_lane = (uint32_t)((lane & 8) << 1);

    float acc[4][4][4];
    #pragma unroll
    for (int i = 0; i < 4; i++)
        #pragma unroll
        for (int j = 0; j < 4; j++)
            #pragma unroll
            for (int q = 0; q < 4; q++) acc[i][j][q] = 0.f;

    load_stage(0);
    load_stage(1);
    load_stage(2);

    for (int s = 0; s < NCHUNK; s++) {
        CP_WAIT2();
        __syncthreads();
        const uint32_t sb = sm_base + (uint32_t)(s % 3) * STG_BYTES;

        #pragma unroll
        for (int ks = 0; ks < 2; ks++) {
            const uint32_t akb = (uint32_t)(ks * 32) + a_kb_lane;
            const uint32_t bkb = (uint32_t)(ks * 32) + b_kb_lane;
            uint32_t fAh[4][4], fAl[4][4], fBh[2][4], fBl[2][4];
            #pragma unroll
            for (int mi = 0; mi < 4; mi++) {
                uint32_t ro  = a_row_off[mi] & 0xFFFFu;
                uint32_t sw  = a_row_off[mi] >> 16;
                uint32_t ad  = sb + ro + (akb ^ sw);
                ldsm4(fAh[mi], ad + OFF_AHI);
                ldsm4(fAl[mi], ad + OFF_ALO);
            }
            #pragma unroll
            for (int g = 0; g < 2; g++) {
                uint32_t ro  = b_row_off[g] & 0xFFFFu;
                uint32_t sw  = b_row_off[g] >> 16;
                uint32_t ad  = sb + ro + (bkb ^ sw);
                ldsm4(fBh[g], ad + OFF_BHI);
                ldsm4(fBl[g], ad + OFF_BLO);
            }
            #pragma unroll
            for (int mi = 0; mi < 4; mi++) {
                #pragma unroll
                for (int nj = 0; nj < 4; nj++) {
                    const uint32_t* bh = &fBh[nj >> 1][(nj & 1) * 2];
                    const uint32_t* bl = &fBl[nj >> 1][(nj & 1) * 2];
                    mma16816(acc[mi][nj], fAh[mi], bh);
                    mma16816(acc[mi][nj], fAh[mi], bl);
                    mma16816(acc[mi][nj], fAl[mi], bh);
                }
            }
        }
        __syncthreads();
        if (s + 3 < NCHUNK) load_stage(s + 3);
    }

    // ---- epilogue ---------------------------------------------------------
    const int mbase = m0 + mw * 64 + (lane >> 2);
    const int nbase = n0 + nw * 32 + 2 * (lane & 3);
    #pragma unroll
    for (int mi = 0; mi < 4; mi++) {
        #pragma unroll
        for (int nj = 0; nj < 4; nj++) {
            const int r0 = mbase + mi * 16;
            const int cc = nbase + nj * 8;
            float b0 = 0.f, b1 = 0.f;
            if (bias) { b0 = __ldg(bias + cc); b1 = __ldg(bias + cc + 1); }
            float2 v0 = make_float2(acc[mi][nj][0] + b0, acc[mi][nj][1] + b1);
            float2 v1 = make_float2(acc[mi][nj][2] + b0, acc[mi][nj][3] + b1);
            *reinterpret_cast<float2*>(C + (size_t)r0 * N + cc)       = v0;
            *reinterpret_cast<float2*>(C + (size_t)(r0 + 8) * N + cc) = v1;
        }
    }
}

// ---------------- fp32 -> bf16 hi/lo split ---------------------------------
__global__ __launch_bounds__(256) void split_kernel(
    const float* __restrict__ src, __nv_bfloat16* __restrict__ hi,
    __nv_bfloat16* __restrict__ lo, int n4)
{
    const int i = blockIdx.x * 256 + threadIdx.x;
    if (i >= n4) return;
    float4 v = reinterpret_cast<const float4*>(src)[i];
    float f[4] = {v.x, v.y, v.z, v.w};
    __nv_bfloat162 h[2], l[2];
    #pragma unroll
    for (int j = 0; j < 2; j++) {
        __nv_bfloat16 h0 = __float2bfloat16(f[2*j]);
        __nv_bfloat16 h1 = __float2bfloat16(f[2*j+1]);
        h[j] = __nv_bfloat162(h0, h1);
        l[j] = __nv_bfloat162(__float2bfloat16(f[2*j]   - __bfloat162float(h0)),
                              __float2bfloat16(f[2*j+1] - __bfloat162float(h1)));
    }
    reinterpret_cast<uint2*>(hi)[i] = *reinterpret_cast<uint2*>(h);
    reinterpret_cast<uint2*>(lo)[i] = *reinterpret_cast<uint2*>(l);
}

// ---------------- norm2 over token axis ------------------------------------
__global__ __launch_bounds__(256) void norm2_kernel(
    const float* __restrict__ W, float* __restrict__ norm2)
{
    const int c  = blockIdx.x * 256 + threadIdx.x;
    const int b  = blockIdx.y;
    const int nc = blockIdx.z;
    const float* p = W + ((size_t)b * NN + (size_t)nc * (NN/8)) * CC + c;
    float s = 0.f;
    #pragma unroll 8
    for (int n = 0; n < NN/8; n++) {
        float v = p[(size_t)n * CC];
        s = fmaf(v, v, s);
    }
    atomicAdd(&norm2[b * CC + c], s);
}

// ---------------- pi + reductions ------------------------------------------
__global__ __launch_bounds__(256) void pi_kernel(
    const float* __restrict__ W, const float* __restrict__ norm2,
    const float* __restrict__ temp,
    float* __restrict__ pi_out, float* __restrict__ dots,
    float* __restrict__ sumpi)
{
    const int tid  = threadIdx.x;
    const int m0   = blockIdx.x * 16;
    const int b    = m0 >> 12;
    const int c0   = tid * 4;
    const int h    = tid >> 4;
    const int lane = tid & 31;

    __shared__ float s_head[16];
    __shared__ float s_pi[16];

    float inv2[4];
    #pragma unroll
    for (int i = 0; i < 4; i++) {
        float nrm = sqrtf(norm2[b * CC + c0 + i]);
        float inv = 1.0f / fmaxf(nrm, 1e-12f);
        inv2[i] = inv * inv;
    }
    const float tmult = temp[h];

    float accD[4] = {0.f, 0.f, 0.f, 0.f};
    float sumPiLoc = 0.f;

    for (int r = 0; r < 16; r++) {
        const int m = m0 + r;
        float4 w4 = *reinterpret_cast<const float4*>(&W[(size_t)m * CC + c0]);
        float sq[4] = {w4.x*w4.x, w4.y*w4.y, w4.z*w4.z, w4.w*w4.w};
        float part = sq[0]*inv2[0] + sq[1]*inv2[1] + sq[2]*inv2[2] + sq[3]*inv2[3];
        part += __shfl_xor_sync(0xffffffffu, part, 8);
        part += __shfl_xor_sync(0xffffffffu, part, 4);
        part += __shfl_xor_sync(0xffffffffu, part, 2);
        part += __shfl_xor_sync(0xffffffffu, part, 1);
        if ((lane & 15) == 0) s_head[h] = part * tmult;
        __syncthreads();
        if (tid < 16) {
            float v  = s_head[tid];
            float mx = v;
            #pragma unroll
            for (int o = 8; o; o >>= 1) mx = fmaxf(mx, __shfl_xor_sync(0x0000ffffu, mx, o));
            float e  = expf(v - mx);
            float se = e;
            #pragma unroll
            for (int o = 8; o; o >>= 1) se += __shfl_xor_sync(0x0000ffffu, se, o);
            float p = e / se;
            s_pi[tid]  = p;
            sumPiLoc  += p;
            pi_out[(size_t)m * HH + tid] = p;
        }
        __syncthreads();
        const float phd = s_pi[h];
        #pragma unroll
        for (int i = 0; i < 4; i++) accD[i] = fmaf(phd, sq[i], accD[i]);
    }

    #pragma unroll
    for (int i = 0; i < 4; i++)
        atomicAdd(&dots[b * CC + c0 + i], accD[i]);
    if (tid < 16)
        atomicAdd(&sumpi[b * HH + tid], sumPiLoc);
}

// ---------------- attn finalize --------------------------------------------
__global__ void attn_kernel(const float* __restrict__ dots,
                            const float* __restrict__ sumpi,
                            float* __restrict__ attn)
{
    const int i = blockIdx.x * 256 + threadIdx.x;
    const int b = i >> 10;
    const int h = (i >> 6) & 15;
    const float dn = dots[i] / (sumpi[b * HH + h] + 1e-8f);
    attn[i] = 1.0f / (1.0f + dn);
}

// ---------------- gate: T = -W * pi * attn, written as bf16 hi/lo ----------
__global__ __launch_bounds__(256) void gate_kernel(
    const float* __restrict__ W, const float* __restrict__ pi,
    const float* __restrict__ attn,
    __nv_bfloat16* __restrict__ Thi, __nv_bfloat16* __restrict__ Tlo)
{
    const size_t idx  = (size_t)blockIdx.x * 256 + threadIdx.x;
    const size_t base = idx * 4;
    const int m = (int)(base >> 10);
    const int c = (int)(base & (CC - 1));
    const int b = m >> 12;
    const int h = c >> 6;
    float4 w4 = *reinterpret_cast<const float4*>(W + base);
    float4 a4 = *reinterpret_cast<const float4*>(attn + b * CC + c);
    const float p = -pi[(size_t)m * HH + h];
    float o[4];
    o[0] = w4.x * p * a4.x;
    o[1] = w4.y * p * a4.y;
    o[2] = w4.z * p * a4.z;
    o[3] = w4.w * p * a4.w;
    __nv_bfloat162 hh[2], ll[2];
    #pragma unroll
    for (int j = 0; j < 2; j++) {
        __nv_bfloat16 h0 = __float2bfloat16(o[2*j]);
        __nv_bfloat16 h1 = __float2bfloat16(o[2*j+1]);
        hh[j] = __nv_bfloat162(h0, h1);
        ll[j] = __nv_bfloat162(__float2bfloat16(o[2*j]   - __bfloat162float(h0)),
                               __float2bfloat16(o[2*j+1] - __bfloat162float(h1)));
    }
    reinterpret_cast<uint2*>(Thi)[idx] = *reinterpret_cast<uint2*>(hh);
    reinterpret_cast<uint2*>(Tlo)[idx] = *reinterpret_cast<uint2*>(ll);
}

// ---------------- launch ---------------------------------------------------
extern "C" void kernel_launch(void* const* d_in, const int* in_sizes, int n_in,
                              void* d_out, int out_size)
{
    const float* x     = (const float*)d_in[0];
    const float* qkv_w = (const float*)d_in[1];
    const float* temp  = (const float*)d_in[2];
    const float* out_w = (const float*)d_in[3];
    const float* out_b = (const float*)d_in[4];
    float* y = (float*)d_out;

    float *W, *pi, *nrm, *dots, *attn, *sp;
    __nv_bfloat16 *Ahi, *Alo, *B1hi, *B1lo, *B2hi, *B2lo;
    cudaGetSymbolAddress((void**)&W,    g_W);
    cudaGetSymbolAddress((void**)&pi,   g_pi);
    cudaGetSymbolAddress((void**)&nrm,  g_norm2);
    cudaGetSymbolAddress((void**)&dots, g_dots);
    cudaGetSymbolAddress((void**)&attn, g_attn);
    cudaGetSymbolAddress((void**)&sp,   g_sumpi);
    cudaGetSymbolAddress((void**)&Ahi,  g_Ahi);
    cudaGetSymbolAddress((void**)&Alo,  g_Alo);
    cudaGetSymbolAddress((void**)&B1hi, g_B1hi);
    cudaGetSymbolAddress((void**)&B1lo, g_B1lo);
    cudaGetSymbolAddress((void**)&B2hi, g_B2hi);
    cudaGetSymbolAddress((void**)&B2lo, g_B2lo);

    cudaFuncSetAttribute(gemm_bf16x3, cudaFuncAttributeMaxDynamicSharedMemorySize, 3 * STG_BYTES);

    cudaMemsetAsync(nrm,  0, BB * CC * sizeof(float));
    cudaMemsetAsync(dots, 0, BB * CC * sizeof(float));
    cudaMemsetAsync(sp,   0, BB * HH * sizeof(float));

    const int n4_big   = (MM * CC) / 4;
    const int n4_small = (CC * CC) / 4;

    split_kernel<<<n4_big / 256, 256>>>(x, Ahi, Alo, n4_big);
    split_kernel<<<n4_small / 256, 256>>>(qkv_w, B1hi, B1lo, n4_small);
    split_kernel<<<n4_small / 256, 256>>>(out_w, B2hi, B2lo, n4_small);

    dim3 ggrid(CC / 128, MM / 128);   // (8, 128)

    // 1) W = x @ qkv_w^T (bf16x3 HMMA)
    gemm_bf16x3<<<ggrid, 256, 3 * STG_BYTES>>>(Ahi, Alo, B1hi, B1lo, nullptr, W, MM, CC, CC);
    // 2) stats
    norm2_kernel<<<dim3(CC / 256, BB, 8), 256>>>(W, nrm);
    pi_kernel<<<MM / 16, 256>>>(W, nrm, temp, pi, dots, sp);
    attn_kernel<<<(BB * CC) / 256, 256>>>(dots, sp, attn);
    // 3) gate -> bf16 hi/lo (reuses Ahi/Alo)
    gate_kernel<<<(int)(((size_t)MM * CC / 4) / 256), 256>>>(W, pi, attn, Ahi, Alo);
    // 4) y = T @ out_w^T + out_b
    gemm_bf16x3<<<ggrid, 256, 3 * STG_BYTES>>>(Ahi, Alo, B2hi, B2lo, out_b, y, MM, CC, CC);
}

// round 6
// speedup vs baseline: 4.2371x; 1.5221x over previous
#include <cuda_runtime.h>
#include <cuda_fp16.h>
#include <cstdint>
#include <math.h>

// Problem constants
#define BB 4
#define NN 4096
#define CC 1024
#define HH 16
#define MM (BB*NN)   // 16384

// ---------------- scratch (device globals; no allocation) ----------------
__device__ float g_W[(size_t)MM * CC];       // qkv projection result fp32
__device__ __half g_Ah[(size_t)MM * CC];     // fp16 of x, later of T
__device__ __half g_B1hi[(size_t)CC * CC];   // qkv_w split hi
__device__ __half g_B1lo[(size_t)CC * CC];   // qkv_w split lo
__device__ __half g_B2hi[(size_t)CC * CC];   // out_w split hi
__device__ __half g_B2lo[(size_t)CC * CC];   // out_w split lo
__device__ float g_pi[(size_t)MM * HH];
__device__ float g_norm2[BB * CC];
__device__ float g_dots[BB * CC];
__device__ float g_attn[BB * CC];
__device__ float g_sumpi[BB * HH];

// ---------------- PTX helpers ---------------------------------------------
__device__ __forceinline__ uint32_t smem_u32(const void* p) {
    uint32_t a;
    asm("{ .reg .u64 t; cvta.to.shared.u64 t, %1; cvt.u32.u64 %0, t; }" : "=r"(a) : "l"(p));
    return a;
}
#define CP_ASYNC16(dst, src) \
    asm volatile("cp.async.cg.shared.global [%0], [%1], 16;" :: "r"(dst), "l"(src) : "memory")
#define CP_COMMIT() asm volatile("cp.async.commit_group;" ::: "memory")
#define CP_WAIT2()  asm volatile("cp.async.wait_group 2;" ::: "memory")

__device__ __forceinline__ void ldsm4(uint32_t* r, uint32_t addr) {
    asm volatile("ldmatrix.sync.aligned.m8n8.x4.shared.b16 {%0,%1,%2,%3}, [%4];"
        : "=r"(r[0]), "=r"(r[1]), "=r"(r[2]), "=r"(r[3]) : "r"(addr));
}
__device__ __forceinline__ void mma16816(float* c, const uint32_t* a, const uint32_t* b) {
    asm volatile("mma.sync.aligned.m16n8k16.row.col.f32.f16.f16.f32 "
        "{%0,%1,%2,%3}, {%4,%5,%6,%7}, {%8,%9}, {%0,%1,%2,%3};"
        : "+f"(c[0]), "+f"(c[1]), "+f"(c[2]), "+f"(c[3])
        : "r"(a[0]), "r"(a[1]), "r"(a[2]), "r"(a[3]), "r"(b[0]), "r"(b[1]));
}

// smem tile: 128 rows x 32 fp16 (64B/row). Swizzle 16B chunks by ((row>>1)&3)<<4.
__device__ __forceinline__ uint32_t tswz(int row, int kb) {
    return (uint32_t)(row * 64 + (kb ^ (((row >> 1) & 3) << 4)));
}

// ---------------- fp16x2 HMMA GEMM: C[m,n] = sum_k A[m,k]*B[n,k] (+bias) --
// Tile 128x128, BK=32, 256 threads (warps 2m x 4n, 64x32 each), 4-stage pipe.
// Terms: A*Bhi + A*Blo. Optional fused norm2 (sum over rows of C^2 per col).
#define STG_BYTES 24576     // 3 sub-tiles x 8KB per stage
#define OFF_A  0
#define OFF_BH 8192
#define OFF_BL 16384
#define NSTG 4

__global__ __launch_bounds__(256, 1) void gemm_fp16x2(
    const __half* __restrict__ A,
    const __half* __restrict__ Bhi, const __half* __restrict__ Blo,
    const float* __restrict__ bias, float* __restrict__ C,
    float* __restrict__ norm2, int M, int N, int K)
{
    extern __shared__ __align__(1024) char smem[];
    const uint32_t sm_base = smem_u32(smem);

    const int tid  = threadIdx.x;
    const int lane = tid & 31;
    const int wid  = tid >> 5;
    const int mw   = wid >> 2;        // 0..1
    const int nw   = wid & 3;         // 0..3
    const int m0   = blockIdx.y * 128;
    const int n0   = blockIdx.x * 128;

    // ---- loader mapping: thread -> (row, 16B chunk) -----------------------
    const int lrow = tid >> 2;        // 0..63
    const int lk16 = tid & 3;         // 0..3
    const uint32_t dst_off0 = tswz(lrow,      lk16 * 16);
    const uint32_t dst_off1 = tswz(lrow + 64, lk16 * 16);
    const char* srcA0  = (const char*)(A   + (size_t)(m0 + lrow)      * K) + lk16 * 16;
    const char* srcA1  = (const char*)(A   + (size_t)(m0 + lrow + 64) * K) + lk16 * 16;
    const char* srcBh0 = (const char*)(Bhi + (size_t)(n0 + lrow)      * K) + lk16 * 16;
    const char* srcBh1 = (const char*)(Bhi + (size_t)(n0 + lrow + 64) * K) + lk16 * 16;
    const char* srcBl0 = (const char*)(Blo + (size_t)(n0 + lrow)      * K) + lk16 * 16;
    const char* srcBl1 = (const char*)(Blo + (size_t)(n0 + lrow + 64) * K) + lk16 * 16;

    const int NCHUNK = K / 32;        // 32

    auto load_stage = [&](int s) {
        const uint32_t sb = sm_base + (uint32_t)(s & (NSTG - 1)) * STG_BYTES;
        const int kb = s * 64;        // byte offset along K
        CP_ASYNC16(sb + OFF_A  + dst_off0, srcA0  + kb);
        CP_ASYNC16(sb + OFF_A  + dst_off1, srcA1  + kb);
        CP_ASYNC16(sb + OFF_BH + dst_off0, srcBh0 + kb);
        CP_ASYNC16(sb + OFF_BH + dst_off1, srcBh1 + kb);
        CP_ASYNC16(sb + OFF_BL + dst_off0, srcBl0 + kb);
        CP_ASYNC16(sb + OFF_BL + dst_off1, srcBl1 + kb);
        CP_COMMIT();
    };

    // ---- per-warp ldmatrix address components -----------------------------
    uint32_t a_row_off[4];
    #pragma unroll
    for (int mi = 0; mi < 4; mi++) {
        int row = mw * 64 + mi * 16 + (lane & 15);
        a_row_off[mi] = (uint32_t)(row * 64);
        a_row_off[mi] |= ((uint32_t)(((row >> 1) & 3) << 4)) << 16;
    }
    const uint32_t a_kb_lane = (uint32_t)((lane >> 4) << 4);
    uint32_t b_row_off[2];
    #pragma unroll
    for (int g = 0; g < 2; g++) {
        int row = nw * 32 + g * 16 + (lane & 7) + ((lane >> 4) << 3);
        b_row_off[g] = (uint32_t)(row * 64);
        b_row_off[g] |= ((uint32_t)(((row >> 1) & 3) << 4)) << 16;
    }
    const uint32_t b_kb_lane = (uint32_t)((lane & 8) << 1);

    float acc[4][4][4];
    #pragma unroll
    for (int i = 0; i < 4; i++)
        #pragma unroll
        for (int j = 0; j < 4; j++)
            #pragma unroll
            for (int q = 0; q < 4; q++) acc[i][j][q] = 0.f;

    load_stage(0);
    load_stage(1);
    load_stage(2);

    for (int s = 0; s < NCHUNK; s++) {
        CP_WAIT2();
        __syncthreads();
        const uint32_t sb = sm_base + (uint32_t)(s & (NSTG - 1)) * STG_BYTES;

        // prefetch all fragments for both ks-steps of this chunk
        uint32_t fA[2][4][4], fBh[2][2][4], fBl[2][2][4];
        #pragma unroll
        for (int ks = 0; ks < 2; ks++) {
            const uint32_t akb = (uint32_t)(ks * 32) + a_kb_lane;
            const uint32_t bkb = (uint32_t)(ks * 32) + b_kb_lane;
            #pragma unroll
            for (int mi = 0; mi < 4; mi++) {
                uint32_t ro = a_row_off[mi] & 0xFFFFu;
                uint32_t sw = a_row_off[mi] >> 16;
                ldsm4(fA[ks][mi], sb + OFF_A + ro + (akb ^ sw));
            }
            #pragma unroll
            for (int g = 0; g < 2; g++) {
                uint32_t ro = b_row_off[g] & 0xFFFFu;
                uint32_t sw = b_row_off[g] >> 16;
                uint32_t ad = sb + ro + (bkb ^ sw);
                ldsm4(fBh[ks][g], ad + OFF_BH);
                ldsm4(fBl[ks][g], ad + OFF_BL);
            }
        }
        #pragma unroll
        for (int ks = 0; ks < 2; ks++) {
            #pragma unroll
            for (int mi = 0; mi < 4; mi++) {
                #pragma unroll
                for (int nj = 0; nj < 4; nj++) {
                    const uint32_t* bh = &fBh[ks][nj >> 1][(nj & 1) * 2];
                    const uint32_t* bl = &fBl[ks][nj >> 1][(nj & 1) * 2];
                    mma16816(acc[mi][nj], fA[ks][mi], bh);
                    mma16816(acc[mi][nj], fA[ks][mi], bl);
                }
            }
        }
        if (s + 3 < NCHUNK) load_stage(s + 3);
        else CP_COMMIT();   // keep group count invariant for the tail waits
    }

    // ---- epilogue ---------------------------------------------------------
    const int mbase = m0 + mw * 64 + (lane >> 2);
    const int nbase = n0 + nw * 32 + 2 * (lane & 3);
    #pragma unroll
    for (int mi = 0; mi < 4; mi++) {
        #pragma unroll
        for (int nj = 0; nj < 4; nj++) {
            const int r0 = mbase + mi * 16;
            const int cc = nbase + nj * 8;
            float b0 = 0.f, b1 = 0.f;
            if (bias) { b0 = __ldg(bias + cc); b1 = __ldg(bias + cc + 1); }
            float2 v0 = make_float2(acc[mi][nj][0] + b0, acc[mi][nj][1] + b1);
            float2 v1 = make_float2(acc[mi][nj][2] + b0, acc[mi][nj][3] + b1);
            *reinterpret_cast<float2*>(C + (size_t)r0 * N + cc)       = v0;
            *reinterpret_cast<float2*>(C + (size_t)(r0 + 8) * N + cc) = v1;
        }
    }

    // ---- fused norm2: sum over this tile's 128 rows of C^2 per column -----
    if (norm2) {
        const int b = m0 >> 12;   // tile fits inside one batch (NN % 128 == 0)
        float cs[4][2];
        #pragma unroll
        for (int nj = 0; nj < 4; nj++) {
            cs[nj][0] = 0.f; cs[nj][1] = 0.f;
            #pragma unroll
            for (int mi = 0; mi < 4; mi++) {
                cs[nj][0] = fmaf(acc[mi][nj][0], acc[mi][nj][0], cs[nj][0]);
                cs[nj][0] = fmaf(acc[mi][nj][2], acc[mi][nj][2], cs[nj][0]);
                cs[nj][1] = fmaf(acc[mi][nj][1], acc[mi][nj][1], cs[nj][1]);
                cs[nj][1] = fmaf(acc[mi][nj][3], acc[mi][nj][3], cs[nj][1]);
            }
        }
        // reduce across the 8 lanes sharing the same columns (lane bits 2..4)
        #pragma unroll
        for (int nj = 0; nj < 4; nj++) {
            #pragma unroll
            for (int t = 0; t < 2; t++) {
                float v = cs[nj][t];
                v += __shfl_xor_sync(0xffffffffu, v, 4);
                v += __shfl_xor_sync(0xffffffffu, v, 8);
                v += __shfl_xor_sync(0xffffffffu, v, 16);
                cs[nj][t] = v;
            }
        }
        if (lane < 4) {
            const int cb = n0 + nw * 32 + 2 * lane;
            #pragma unroll
            for (int nj = 0; nj < 4; nj++) {
                atomicAdd(&norm2[b * CC + cb + nj * 8],     cs[nj][0]);
                atomicAdd(&norm2[b * CC + cb + nj * 8 + 1], cs[nj][1]);
            }
        }
    }
}

// ---------------- fp32 -> fp16 cast (activations) --------------------------
__global__ __launch_bounds__(256) void cast_fp16_kernel(
    const float* __restrict__ src, __half* __restrict__ dst, int n4)
{
    const int i = blockIdx.x * 256 + threadIdx.x;
    if (i >= n4) return;
    float4 v = reinterpret_cast<const float4*>(src)[i];
    __half2 h[2];
    h[0] = __halves2half2(__float2half_rn(v.x), __float2half_rn(v.y));
    h[1] = __halves2half2(__float2half_rn(v.z), __float2half_rn(v.w));
    reinterpret_cast<uint2*>(dst)[i] = *reinterpret_cast<uint2*>(h);
}

// ---------------- fp32 -> fp16 hi/lo split (weights) -----------------------
__global__ __launch_bounds__(256) void split_fp16_kernel(
    const float* __restrict__ src, __half* __restrict__ hi,
    __half* __restrict__ lo, int n4)
{
    const int i = blockIdx.x * 256 + threadIdx.x;
    if (i >= n4) return;
    float4 v = reinterpret_cast<const float4*>(src)[i];
    float f[4] = {v.x, v.y, v.z, v.w};
    __half2 h[2], l[2];
    #pragma unroll
    for (int j = 0; j < 2; j++) {
        __half h0 = __float2half_rn(f[2*j]);
        __half h1 = __float2half_rn(f[2*j+1]);
        h[j] = __halves2half2(h0, h1);
        l[j] = __halves2half2(__float2half_rn(f[2*j]   - __half2float(h0)),
                              __float2half_rn(f[2*j+1] - __half2float(h1)));
    }
    reinterpret_cast<uint2*>(hi)[i] = *reinterpret_cast<uint2*>(h);
    reinterpret_cast<uint2*>(lo)[i] = *reinterpret_cast<uint2*>(l);
}

// ---------------- pi + reductions ------------------------------------------
__global__ __launch_bounds__(256) void pi_kernel(
    const float* __restrict__ W, const float* __restrict__ norm2,
    const float* __restrict__ temp,
    float* __restrict__ pi_out, float* __restrict__ dots,
    float* __restrict__ sumpi)
{
    const int tid  = threadIdx.x;
    const int m0   = blockIdx.x * 16;
    const int b    = m0 >> 12;
    const int c0   = tid * 4;
    const int h    = tid >> 4;
    const int lane = tid & 31;

    __shared__ float s_head[16];
    __shared__ float s_pi[16];

    float inv2[4];
    #pragma unroll
    for (int i = 0; i < 4; i++) {
        float nrm = sqrtf(norm2[b * CC + c0 + i]);
        float inv = 1.0f / fmaxf(nrm, 1e-12f);
        inv2[i] = inv * inv;
    }
    const float tmult = temp[h];

    float accD[4] = {0.f, 0.f, 0.f, 0.f};
    float sumPiLoc = 0.f;

    for (int r = 0; r < 16; r++) {
        const int m = m0 + r;
        float4 w4 = *reinterpret_cast<const float4*>(&W[(size_t)m * CC + c0]);
        float sq[4] = {w4.x*w4.x, w4.y*w4.y, w4.z*w4.z, w4.w*w4.w};
        float part = sq[0]*inv2[0] + sq[1]*inv2[1] + sq[2]*inv2[2] + sq[3]*inv2[3];
        part += __shfl_xor_sync(0xffffffffu, part, 8);
        part += __shfl_xor_sync(0xffffffffu, part, 4);
        part += __shfl_xor_sync(0xffffffffu, part, 2);
        part += __shfl_xor_sync(0xffffffffu, part, 1);
        if ((lane & 15) == 0) s_head[h] = part * tmult;
        __syncthreads();
        if (tid < 16) {
            float v  = s_head[tid];
            float mx = v;
            #pragma unroll
            for (int o = 8; o; o >>= 1) mx = fmaxf(mx, __shfl_xor_sync(0x0000ffffu, mx, o));
            float e  = expf(v - mx);
            float se = e;
            #pragma unroll
            for (int o = 8; o; o >>= 1) se += __shfl_xor_sync(0x0000ffffu, se, o);
            float p = e / se;
            s_pi[tid]  = p;
            sumPiLoc  += p;
            pi_out[(size_t)m * HH + tid] = p;
        }
        __syncthreads();
        const float phd = s_pi[h];
        #pragma unroll
        for (int i = 0; i < 4; i++) accD[i] = fmaf(phd, sq[i], accD[i]);
    }

    #pragma unroll
    for (int i = 0; i < 4; i++)
        atomicAdd(&dots[b * CC + c0 + i], accD[i]);
    if (tid < 16)
        atomicAdd(&sumpi[b * HH + tid], sumPiLoc);
}

// ---------------- attn finalize --------------------------------------------
__global__ void attn_kernel(const float* __restrict__ dots,
                            const float* __restrict__ sumpi,
                            float* __restrict__ attn)
{
    const int i = blockIdx.x * 256 + threadIdx.x;
    const int b = i >> 10;
    const int h = (i >> 6) & 15;
    const float dn = dots[i] / (sumpi[b * HH + h] + 1e-8f);
    attn[i] = 1.0f / (1.0f + dn);
}

// ---------------- gate: T = -W * pi * attn, written as fp16 ----------------
__global__ __launch_bounds__(256) void gate_kernel(
    const float* __restrict__ W, const float* __restrict__ pi,
    const float* __restrict__ attn, __half* __restrict__ Th)
{
    const size_t idx  = (size_t)blockIdx.x * 256 + threadIdx.x;
    const size_t base = idx * 4;
    const int m = (int)(base >> 10);
    const int c = (int)(base & (CC - 1));
    const int b = m >> 12;
    const int h = c >> 6;
    float4 w4 = *reinterpret_cast<const float4*>(W + base);
    float4 a4 = *reinterpret_cast<const float4*>(attn + b * CC + c);
    const float p = -pi[(size_t)m * HH + h];
    __half2 o[2];
    o[0] = __halves2half2(__float2half_rn(w4.x * p * a4.x),
                          __float2half_rn(w4.y * p * a4.y));
    o[1] = __halves2half2(__float2half_rn(w4.z * p * a4.z),
                          __float2half_rn(w4.w * p * a4.w));
    reinterpret_cast<uint2*>(Th)[idx] = *reinterpret_cast<uint2*>(o);
}

// ---------------- launch ---------------------------------------------------
extern "C" void kernel_launch(void* const* d_in, const int* in_sizes, int n_in,
                              void* d_out, int out_size)
{
    const float* x     = (const float*)d_in[0];
    const float* qkv_w = (const float*)d_in[1];
    const float* temp  = (const float*)d_in[2];
    const float* out_w = (const float*)d_in[3];
    const float* out_b = (const float*)d_in[4];
    float* y = (float*)d_out;

    float *W, *pi, *nrm, *dots, *attn, *sp;
    __half *Ah, *B1hi, *B1lo, *B2hi, *B2lo;
    cudaGetSymbolAddress((void**)&W,    g_W);
    cudaGetSymbolAddress((void**)&pi,   g_pi);
    cudaGetSymbolAddress((void**)&nrm,  g_norm2);
    cudaGetSymbolAddress((void**)&dots, g_dots);
    cudaGetSymbolAddress((void**)&attn, g_attn);
    cudaGetSymbolAddress((void**)&sp,   g_sumpi);
    cudaGetSymbolAddress((void**)&Ah,   g_Ah);
    cudaGetSymbolAddress((void**)&B1hi, g_B1hi);
    cudaGetSymbolAddress((void**)&B1lo, g_B1lo);
    cudaGetSymbolAddress((void**)&B2hi, g_B2hi);
    cudaGetSymbolAddress((void**)&B2lo, g_B2lo);

    cudaFuncSetAttribute(gemm_fp16x2, cudaFuncAttributeMaxDynamicSharedMemorySize, NSTG * STG_BYTES);

    cudaMemsetAsync(nrm,  0, BB * CC * sizeof(float));
    cudaMemsetAsync(dots, 0, BB * CC * sizeof(float));
    cudaMemsetAsync(sp,   0, BB * HH * sizeof(float));

    const int n4_big   = (MM * CC) / 4;
    const int n4_small = (CC * CC) / 4;

    cast_fp16_kernel<<<n4_big / 256, 256>>>(x, Ah, n4_big);
    split_fp16_kernel<<<n4_small / 256, 256>>>(qkv_w, B1hi, B1lo, n4_small);
    split_fp16_kernel<<<n4_small / 256, 256>>>(out_w, B2hi, B2lo, n4_small);

    dim3 ggrid(CC / 128, MM / 128);   // (8, 128)

    // 1) W = x @ qkv_w^T (fp16x2 HMMA) + fused norm2
    gemm_fp16x2<<<ggrid, 256, NSTG * STG_BYTES>>>(Ah, B1hi, B1lo, nullptr, W, nrm, MM, CC, CC);
    // 2) stats
    pi_kernel<<<MM / 16, 256>>>(W, nrm, temp, pi, dots, sp);
    attn_kernel<<<(BB * CC) / 256, 256>>>(dots, sp, attn);
    // 3) gate -> fp16 (reuses Ah)
    gate_kernel<<<(int)(((size_t)MM * CC / 4) / 256), 256>>>(W, pi, attn, Ah);
    // 4) y = T @ out_w^T + out_b
    gemm_fp16x2<<<ggrid, 256, NSTG * STG_BYTES>>>(Ah, B2hi, B2lo, out_b, y, nullptr, MM, CC, CC);
}

// round 8
// speedup vs baseline: 6.9379x; 1.6374x over previous
#include <cuda_runtime.h>
#include <cuda_fp16.h>
#include <cstdint>
#include <math.h>

// Problem constants
#define BB 4
#define NN 4096
#define CC 1024
#define HH 16
#define MM (BB*NN)   // 16384

// ---------------- scratch (device globals; no allocation) ----------------
__device__ float g_W[(size_t)MM * CC];       // qkv projection result fp32
__device__ __half g_Ah[(size_t)MM * CC];     // fp16 of x, later of T
__device__ __half g_B1[(size_t)CC * CC];     // qkv_w fp16
__device__ __half g_B2[(size_t)CC * CC];     // out_w fp16
__device__ float g_pi[(size_t)MM * HH];
__device__ float g_norm2[BB * CC];
__device__ float g_dots[BB * CC];
__device__ float g_attn[BB * CC];
__device__ float g_sumpi[BB * HH];

// ---------------- PTX helpers ---------------------------------------------
__device__ __forceinline__ uint32_t smem_u32(const void* p) {
    uint32_t a;
    asm("{ .reg .u64 t; cvta.to.shared.u64 t, %1; cvt.u32.u64 %0, t; }" : "=r"(a) : "l"(p));
    return a;
}
#define CP_ASYNC16(dst, src) \
    asm volatile("cp.async.cg.shared.global [%0], [%1], 16;" :: "r"(dst), "l"(src) : "memory")
#define CP_COMMIT() asm volatile("cp.async.commit_group;" ::: "memory")
#define CP_WAIT2()  asm volatile("cp.async.wait_group 2;" ::: "memory")

__device__ __forceinline__ void ldsm4(uint32_t* r, uint32_t addr) {
    asm volatile("ldmatrix.sync.aligned.m8n8.x4.shared.b16 {%0,%1,%2,%3}, [%4];"
        : "=r"(r[0]), "=r"(r[1]), "=r"(r[2]), "=r"(r[3]) : "r"(addr));
}
__device__ __forceinline__ void mma16816(float* c, const uint32_t* a, const uint32_t* b) {
    asm volatile("mma.sync.aligned.m16n8k16.row.col.f32.f16.f16.f32 "
        "{%0,%1,%2,%3}, {%4,%5,%6,%7}, {%8,%9}, {%0,%1,%2,%3};"
        : "+f"(c[0]), "+f"(c[1]), "+f"(c[2]), "+f"(c[3])
        : "r"(a[0]), "r"(a[1]), "r"(a[2]), "r"(a[3]), "r"(b[0]), "r"(b[1]));
}

// smem tile: 128 rows x 32 fp16 (64B/row). Swizzle 16B chunks by ((row>>1)&3)<<4.
__device__ __forceinline__ uint32_t tswz(int row, int kb) {
    return (uint32_t)(row * 64 + (kb ^ (((row >> 1) & 3) << 4)));
}

// ---------------- fp16 HMMA GEMM: C[m,n] = sum_k A[m,k]*B[n,k] (+bias) ----
// Tile 128x128, BK=32, 256 threads (warps 2m x 4n, 64x32 each), 4-stage pipe.
// 2 CTAs/SM (regs capped at 128, 64KB smem per CTA).
#define STG_BYTES 16384     // 2 sub-tiles x 8KB per stage
#define OFF_A  0
#define OFF_B  8192
#define NSTG 4

__global__ __launch_bounds__(256, 2) void gemm_fp16(
    const __half* __restrict__ A, const __half* __restrict__ B,
    const float* __restrict__ bias, float* __restrict__ C,
    float* __restrict__ norm2, int M, int N, int K)
{
    extern __shared__ __align__(1024) char smem[];
    const uint32_t sm_base = smem_u32(smem);

    const int tid  = threadIdx.x;
    const int lane = tid & 31;
    const int wid  = tid >> 5;
    const int mw   = wid >> 2;        // 0..1
    const int nw   = wid & 3;         // 0..3
    const int m0   = blockIdx.y * 128;
    const int n0   = blockIdx.x * 128;

    // ---- loader mapping: thread -> (row, 16B chunk) -----------------------
    const int lrow = tid >> 2;        // 0..63
    const int lk16 = tid & 3;         // 0..3
    const uint32_t dst_off0 = tswz(lrow,      lk16 * 16);
    const uint32_t dst_off1 = tswz(lrow + 64, lk16 * 16);
    const char* srcA0 = (const char*)(A + (size_t)(m0 + lrow)      * K) + lk16 * 16;
    const char* srcA1 = (const char*)(A + (size_t)(m0 + lrow + 64) * K) + lk16 * 16;
    const char* srcB0 = (const char*)(B + (size_t)(n0 + lrow)      * K) + lk16 * 16;
    const char* srcB1 = (const char*)(B + (size_t)(n0 + lrow + 64) * K) + lk16 * 16;

    const int NCHUNK = K / 32;        // 32

    auto load_stage = [&](int s) {
        const uint32_t sb = sm_base + (uint32_t)(s & (NSTG - 1)) * STG_BYTES;
        const int kb = s * 64;        // byte offset along K
        CP_ASYNC16(sb + OFF_A + dst_off0, srcA0 + kb);
        CP_ASYNC16(sb + OFF_A + dst_off1, srcA1 + kb);
        CP_ASYNC16(sb + OFF_B + dst_off0, srcB0 + kb);
        CP_ASYNC16(sb + OFF_B + dst_off1, srcB1 + kb);
        CP_COMMIT();
    };

    // ---- per-warp ldmatrix address components -----------------------------
    uint32_t a_row_off[4];
    #pragma unroll
    for (int mi = 0; mi < 4; mi++) {
        int row = mw * 64 + mi * 16 + (lane & 15);
        a_row_off[mi] = (uint32_t)(row * 64);
        a_row_off[mi] |= ((uint32_t)(((row >> 1) & 3) << 4)) << 16;
    }
    const uint32_t a_kb_lane = (uint32_t)((lane >> 4) << 4);
    uint32_t b_row_off[2];
    #pragma unroll
    for (int g = 0; g < 2; g++) {
        int row = nw * 32 + g * 16 + (lane & 7) + ((lane >> 4) << 3);
        b_row_off[g] = (uint32_t)(row * 64);
        b_row_off[g] |= ((uint32_t)(((row >> 1) & 3) << 4)) << 16;
    }
    const uint32_t b_kb_lane = (uint32_t)((lane & 8) << 1);

    float acc[4][4][4];
    #pragma unroll
    for (int i = 0; i < 4; i++)
        #pragma unroll
        for (int j = 0; j < 4; j++)
            #pragma unroll
            for (int q = 0; q < 4; q++) acc[i][j][q] = 0.f;

    load_stage(0);
    load_stage(1);
    load_stage(2);

    for (int s = 0; s < NCHUNK; s++) {
        CP_WAIT2();
        __syncthreads();
        const uint32_t sb = sm_base + (uint32_t)(s & (NSTG - 1)) * STG_BYTES;

        #pragma unroll
        for (int ks = 0; ks < 2; ks++) {
            const uint32_t akb = (uint32_t)(ks * 32) + a_kb_lane;
            const uint32_t bkb = (uint32_t)(ks * 32) + b_kb_lane;
            uint32_t fA[4][4], fB[2][4];
            #pragma unroll
            for (int mi = 0; mi < 4; mi++) {
                uint32_t ro = a_row_off[mi] & 0xFFFFu;
                uint32_t sw = a_row_off[mi] >> 16;
                ldsm4(fA[mi], sb + OFF_A + ro + (akb ^ sw));
            }
            #pragma unroll
            for (int g = 0; g < 2; g++) {
                uint32_t ro = b_row_off[g] & 0xFFFFu;
                uint32_t sw = b_row_off[g] >> 16;
                ldsm4(fB[g], sb + OFF_B + ro + (bkb ^ sw));
            }
            #pragma unroll
            for (int mi = 0; mi < 4; mi++) {
                #pragma unroll
                for (int nj = 0; nj < 4; nj++) {
                    mma16816(acc[mi][nj], fA[mi], &fB[nj >> 1][(nj & 1) * 2]);
                }
            }
        }
        if (s + 3 < NCHUNK) load_stage(s + 3);
        else CP_COMMIT();   // keep group count invariant for the tail waits
    }

    // ---- epilogue ---------------------------------------------------------
    const int mbase = m0 + mw * 64 + (lane >> 2);
    const int nbase = n0 + nw * 32 + 2 * (lane & 3);
    #pragma unroll
    for (int mi = 0; mi < 4; mi++) {
        #pragma unroll
        for (int nj = 0; nj < 4; nj++) {
            const int r0 = mbase + mi * 16;
            const int cc = nbase + nj * 8;
            float b0 = 0.f, b1 = 0.f;
            if (bias) { b0 = __ldg(bias + cc); b1 = __ldg(bias + cc + 1); }
            float2 v0 = make_float2(acc[mi][nj][0] + b0, acc[mi][nj][1] + b1);
            float2 v1 = make_float2(acc[mi][nj][2] + b0, acc[mi][nj][3] + b1);
            *reinterpret_cast<float2*>(C + (size_t)r0 * N + cc)       = v0;
            *reinterpret_cast<float2*>(C + (size_t)(r0 + 8) * N + cc) = v1;
        }
    }

    // ---- fused norm2: sum over this tile's 128 rows of C^2 per column -----
    if (norm2) {
        const int b = m0 >> 12;   // tile fits inside one batch (NN % 128 == 0)
        float cs[4][2];
        #pragma unroll
        for (int nj = 0; nj < 4; nj++) {
            cs[nj][0] = 0.f; cs[nj][1] = 0.f;
            #pragma unroll
            for (int mi = 0; mi < 4; mi++) {
                cs[nj][0] = fmaf(acc[mi][nj][0], acc[mi][nj][0], cs[nj][0]);
                cs[nj][0] = fmaf(acc[mi][nj][2], acc[mi][nj][2], cs[nj][0]);
                cs[nj][1] = fmaf(acc[mi][nj][1], acc[mi][nj][1], cs[nj][1]);
                cs[nj][1] = fmaf(acc[mi][nj][3], acc[mi][nj][3], cs[nj][1]);
            }
        }
        #pragma unroll
        for (int nj = 0; nj < 4; nj++) {
            #pragma unroll
            for (int t = 0; t < 2; t++) {
                float v = cs[nj][t];
                v += __shfl_xor_sync(0xffffffffu, v, 4);
                v += __shfl_xor_sync(0xffffffffu, v, 8);
                v += __shfl_xor_sync(0xffffffffu, v, 16);
                cs[nj][t] = v;
            }
        }
        if (lane < 4) {
            const int cb = n0 + nw * 32 + 2 * lane;
            #pragma unroll
            for (int nj = 0; nj < 4; nj++) {
                atomicAdd(&norm2[b * CC + cb + nj * 8],     cs[nj][0]);
                atomicAdd(&norm2[b * CC + cb + nj * 8 + 1], cs[nj][1]);
            }
        }
    }
}

// ---------------- fp32 -> fp16 cast ----------------------------------------
__global__ __launch_bounds__(256) void cast_fp16_kernel(
    const float* __restrict__ src, __half* __restrict__ dst, int n4)
{
    const int i = blockIdx.x * 256 + threadIdx.x;
    if (i >= n4) return;
    float4 v = reinterpret_cast<const float4*>(src)[i];
    __half2 h[2];
    h[0] = __halves2half2(__float2half_rn(v.x), __float2half_rn(v.y));
    h[1] = __halves2half2(__float2half_rn(v.z), __float2half_rn(v.w));
    reinterpret_cast<uint2*>(dst)[i] = *reinterpret_cast<uint2*>(h);
}

// ---------------- pi + reductions ------------------------------------------
__global__ __launch_bounds__(256) void pi_kernel(
    const float* __restrict__ W, const float* __restrict__ norm2,
    const float* __restrict__ temp,
    float* __restrict__ pi_out, float* __restrict__ dots,
    float* __restrict__ sumpi)
{
    const int tid  = threadIdx.x;
    const int m0   = blockIdx.x * 16;
    const int b    = m0 >> 12;
    const int c0   = tid * 4;
    const int h    = tid >> 4;
    const int lane = tid & 31;

    __shared__ float s_head[16];
    __shared__ float s_pi[16];

    float inv2[4];
    #pragma unroll
    for (int i = 0; i < 4; i++) {
        float nrm = sqrtf(norm2[b * CC + c0 + i]);
        float inv = 1.0f / fmaxf(nrm, 1e-12f);
        inv2[i] = inv * inv;
    }
    const float tmult = temp[h];

    float accD[4] = {0.f, 0.f, 0.f, 0.f};
    float sumPiLoc = 0.f;

    for (int r = 0; r < 16; r++) {
        const int m = m0 + r;
        float4 w4 = *reinterpret_cast<const float4*>(&W[(size_t)m * CC + c0]);
        float sq[4] = {w4.x*w4.x, w4.y*w4.y, w4.z*w4.z, w4.w*w4.w};
        float part = sq[0]*inv2[0] + sq[1]*inv2[1] + sq[2]*inv2[2] + sq[3]*inv2[3];
        part += __shfl_xor_sync(0xffffffffu, part, 8);
        part += __shfl_xor_sync(0xffffffffu, part, 4);
        part += __shfl_xor_sync(0xffffffffu, part, 2);
        part += __shfl_xor_sync(0xffffffffu, part, 1);
        if ((lane & 15) == 0) s_head[h] = part * tmult;
        __syncthreads();
        if (tid < 16) {
            float v  = s_head[tid];
            float mx = v;
            #pragma unroll
            for (int o = 8; o; o >>= 1) mx = fmaxf(mx, __shfl_xor_sync(0x0000ffffu, mx, o));
            float e  = expf(v - mx);
            float se = e;
            #pragma unroll
            for (int o = 8; o; o >>= 1) se += __shfl_xor_sync(0x0000ffffu, se, o);
            float p = e / se;
            s_pi[tid]  = p;
            sumPiLoc  += p;
            pi_out[(size_t)m * HH + tid] = p;
        }
        __syncthreads();
        const float phd = s_pi[h];
        #pragma unroll
        for (int i = 0; i < 4; i++) accD[i] = fmaf(phd, sq[i], accD[i]);
    }

    #pragma unroll
    for (int i = 0; i < 4; i++)
        atomicAdd(&dots[b * CC + c0 + i], accD[i]);
    if (tid < 16)
        atomicAdd(&sumpi[b * HH + tid], sumPiLoc);
}

// ---------------- attn finalize --------------------------------------------
__global__ void attn_kernel(const float* __restrict__ dots,
                            const float* __restrict__ sumpi,
                            float* __restrict__ attn)
{
    const int i = blockIdx.x * 256 + threadIdx.x;
    const int b = i >> 10;
    const int h = (i >> 6) & 15;
    const float dn = dots[i] / (sumpi[b * HH + h] + 1e-8f);
    attn[i] = 1.0f / (1.0f + dn);
}

// ---------------- gate: T = -W * pi * attn, written as fp16 ----------------
__global__ __launch_bounds__(256) void gate_kernel(
    const float* __restrict__ W, const float* __restrict__ pi,
    const float* __restrict__ attn, __half* __restrict__ Th)
{
    const size_t idx  = (size_t)blockIdx.x * 256 + threadIdx.x;
    const size_t base = idx * 4;
    const int m = (int)(base >> 10);
    const int c = (int)(base & (CC - 1));
    const int b = m >> 12;
    const int h = c >> 6;
    float4 w4 = *reinterpret_cast<const float4*>(W + base);
    float4 a4 = *reinterpret_cast<const float4*>(attn + b * CC + c);
    const float p = -pi[(size_t)m * HH + h];
    __half2 o[2];
    o[0] = __halves2half2(__float2half_rn(w4.x * p * a4.x),
                          __float2half_rn(w4.y * p * a4.y));
    o[1] = __halves2half2(__float2half_rn(w4.z * p * a4.z),
                          __float2half_rn(w4.w * p * a4.w));
    reinterpret_cast<uint2*>(Th)[idx] = *reinterpret_cast<uint2*>(o);
}

// ---------------- launch ---------------------------------------------------
extern "C" void kernel_launch(void* const* d_in, const int* in_sizes, int n_in,
                              void* d_out, int out_size)
{
    const float* x     = (const float*)d_in[0];
    const float* qkv_w = (const float*)d_in[1];
    const float* temp  = (const float*)d_in[2];
    const float* out_w = (const float*)d_in[3];
    const float* out_b = (const float*)d_in[4];
    float* y = (float*)d_out;

    float *W, *pi, *nrm, *dots, *attn, *sp;
    __half *Ah, *B1, *B2;
    cudaGetSymbolAddress((void**)&W,    g_W);
    cudaGetSymbolAddress((void**)&pi,   g_pi);
    cudaGetSymbolAddress((void**)&nrm,  g_norm2);
    cudaGetSymbolAddress((void**)&dots, g_dots);
    cudaGetSymbolAddress((void**)&attn, g_attn);
    cudaGetSymbolAddress((void**)&sp,   g_sumpi);
    cudaGetSymbolAddress((void**)&Ah,   g_Ah);
    cudaGetSymbolAddress((void**)&B1,   g_B1);
    cudaGetSymbolAddress((void**)&B2,   g_B2);

    cudaFuncSetAttribute(gemm_fp16, cudaFuncAttributeMaxDynamicSharedMemorySize, NSTG * STG_BYTES);

    cudaMemsetAsync(nrm,  0, BB * CC * sizeof(float));
    cudaMemsetAsync(dots, 0, BB * CC * sizeof(float));
    cudaMemsetAsync(sp,   0, BB * HH * sizeof(float));

    const int n4_big   = (MM * CC) / 4;
    const int n4_small = (CC * CC) / 4;

    cast_fp16_kernel<<<n4_big / 256, 256>>>(x, Ah, n4_big);
    cast_fp16_kernel<<<n4_small / 256, 256>>>(qkv_w, B1, n4_small);
    cast_fp16_kernel<<<n4_small / 256, 256>>>(out_w, B2, n4_small);

    dim3 ggrid(CC / 128, MM / 128);   // (8, 128)

    // 1) W = x @ qkv_w^T (fp16 HMMA) + fused norm2
    gemm_fp16<<<ggrid, 256, NSTG * STG_BYTES>>>(Ah, B1, nullptr, W, nrm, MM, CC, CC);
    // 2) stats
    pi_kernel<<<MM / 16, 256>>>(W, nrm, temp, pi, dots, sp);
    attn_kernel<<<(BB * CC) / 256, 256>>>(dots, sp, attn);
    // 3) gate -> fp16 (reuses Ah)
    gate_kernel<<<(int)(((size_t)MM * CC / 4) / 256), 256>>>(W, pi, attn, Ah);
    // 4) y = T @ out_w^T + out_b
    gemm_fp16<<<ggrid, 256, NSTG * STG_BYTES>>>(Ah, B2, out_b, y, nullptr, MM, CC, CC);
}